// round 17
// baseline (speedup 1.0000x reference)
#include <cuda_runtime.h>
#include <cuda_bf16.h>
#include <cstdint>

// ============================ problem constants ============================
#define B_SZ   32
#define S_SZ   4096
#define E_SZ   256
#define A_SZ   256
#define NROWS  (S_SZ * B_SZ)       // 131072 rows, row r = s*32 + b
#define TILE_M 128
#define NTILES (NROWS / TILE_M)    // 1024
#define NCHUNK 64                  // a-columns per chunk
#define NCH    (A_SZ / NCHUNK)     // 4 chunks
#define NSC    16                  // attn s-chunks

// ============================ device scratch ===============================
__device__ uint2 g_whe[A_SZ * E_SZ / 4];   // bf16 hi of We, [a][e] row-major (512B rows)
__device__ uint2 g_wle[A_SZ * E_SZ / 4];   // bf16 lo of We
__device__ float g_proj[B_SZ * A_SZ];      // proj[b][a]
__device__ float g_scoresT[B_SZ * S_SZ];   // scores[b][s]  (transposed)
__device__ float g_normT[B_SZ * S_SZ];     // ||eo[s,b,:]|| as [b][s]
__device__ float g_smax[B_SZ];
__device__ float g_sinv[B_SZ];
__device__ float g_attpart[B_SZ * NSC * E_SZ];

// ============================ helpers ======================================
__device__ __forceinline__ uint32_t smem_u32(const void* p) {
    uint32_t a;
    asm("{ .reg .u64 t; cvta.to.shared.u64 t, %1; cvt.u32.u64 %0, t; }" : "=r"(a) : "l"(p));
    return a;
}
__device__ __forceinline__ void cp16(uint32_t dst, const void* src) {
    asm volatile("cp.async.cg.shared.global [%0], [%1], 16;" :: "r"(dst), "l"(src));
}
__device__ __forceinline__ void cp_commit() {
    asm volatile("cp.async.commit_group;" ::: "memory");
}
__device__ __forceinline__ void cp_wait0() {
    asm volatile("cp.async.wait_group 0;" ::: "memory");
}
__device__ __forceinline__ void ldsm4(uint32_t (&r)[4], uint32_t addr) {
    asm volatile("ldmatrix.sync.aligned.m8n8.x4.shared.b16 {%0,%1,%2,%3}, [%4];"
                 : "=r"(r[0]), "=r"(r[1]), "=r"(r[2]), "=r"(r[3]) : "r"(addr));
}
__device__ __forceinline__ void mma16816(float (&c)[4], const uint32_t (&a)[4],
                                         uint32_t b0, uint32_t b1) {
    asm volatile(
        "mma.sync.aligned.m16n8k16.row.col.f32.bf16.bf16.f32 "
        "{%0,%1,%2,%3}, {%4,%5,%6,%7}, {%8,%9}, {%0,%1,%2,%3};"
        : "+f"(c[0]), "+f"(c[1]), "+f"(c[2]), "+f"(c[3])
        : "r"(a[0]), "r"(a[1]), "r"(a[2]), "r"(a[3]), "r"(b0), "r"(b1));
}
// fast accurate tanh: 2 MUFU (EX2 + RCP), abs err ~1e-6
__device__ __forceinline__ float tanh_fast(float x) {
    float xc = fminf(fmaxf(x, -15.f), 15.f);
    float u  = __expf(xc + xc);
    return __fdividef(u - 1.f, u + 1.f);
}
__device__ __forceinline__ uint32_t packbf2f(float a, float b) {
    __nv_bfloat162 h = __float22bfloat162_rn(make_float2(a, b));
    return *(uint32_t*)&h;
}

// ============================ kernel 1: split We ===========================
__global__ void splitw_kernel(const float* __restrict__ W) {
    int i = blockIdx.x * 256 + threadIdx.x;     // 65536 = A*E
    int a = i >> 8, e = i & 255;
    float w = W[a * 512 + 256 + e];             // We = W[:, 256:512]
    __nv_bfloat16 h = __float2bfloat16(w);
    float lo = w - __bfloat162float(h);
    ((__nv_bfloat16*)g_whe)[i] = h;
    ((__nv_bfloat16*)g_wle)[i] = __float2bfloat16(lo);
}

// ============================ kernel 2: proj ===============================
__global__ void proj_kernel(const float* __restrict__ dh, const float* __restrict__ W,
                            const float* __restrict__ bias) {
    int b = blockIdx.x, a = threadIdx.x;
    __shared__ float dsh[256];
    dsh[a] = dh[b * 256 + a];
    __syncthreads();
    const float4* wr = (const float4*)(W + a * 512);   // Wd row of thread's a
    float acc = bias[a];
#pragma unroll 8
    for (int d4 = 0; d4 < 64; d4++) {
        float4 w = wr[d4];
        acc += w.x * dsh[d4 * 4 + 0] + w.y * dsh[d4 * 4 + 1]
             + w.z * dsh[d4 * 4 + 2] + w.w * dsh[d4 * 4 + 3];
    }
    g_proj[b * 256 + a] = acc;
}

// ==== profiling slot shim: puts phase1 at the ncu-captured launch index ====
__global__ void dummy_kernel() {}

// ========== kernel 3: fused GEMM (HMMA bf16 3-split) + tanh + rowsum =======
// TILE_M=128, 1 CTA/SM, 8 warps. Warp tile m32 x n32, FULL k256 per warp
// (no k-split, no ACC combine). We chunk = 64 a-rows, single-buffered.
// smem: A_hi [128][256]bf16 swizzled (64KB), A_lo (64KB), W hi+lo (64KB),
// score partials (1KB). nsq partials overlay W buffer pre-MMA.
#define OFF_AH   0
#define OFF_AL   65536
#define OFF_W    131072                 // hi 32768 + lo 32768
#define OFF_SC   196608                 // 2 x 128 floats
#define SMEM_P1  (OFF_SC + 1024)        // 197632 bytes

__device__ __forceinline__ void prefetch_w(uint32_t sb, int chunk, int tid) {
    const int a0 = chunk * NCHUNK;
#pragma unroll
    for (int it = 0; it < 8; it++) {
        int idx = it * 256 + tid;               // 0..2047
        int n = idx >> 5, ck = idx & 31;
        uint32_t dst = (uint32_t)(n * 512 + ((ck ^ (n & 7)) << 4));
        cp16(sb + OFF_W + dst,         g_whe + (a0 + n) * 64 + ck * 2);
        cp16(sb + OFF_W + 32768 + dst, g_wle + (a0 + n) * 64 + ck * 2);
    }
    cp_commit();
}

__global__ void __launch_bounds__(256, 1) phase1_kernel(const float* __restrict__ eo) {
    extern __shared__ char smem[];
    const uint32_t sb  = smem_u32(smem);
    const int tid  = threadIdx.x;
    const int lane = tid & 31;
    const int w    = tid >> 5;
    const int r0   = blockIdx.x * TILE_M;

    float* nsq_part = (float*)(smem + OFF_W);     // [128][65] overlay (pre-MMA only)
    float* sc_part  = (float*)(smem + OFF_SC);    // [2][128]

    // ---- load eo tile (128 x 256 f32) -> bf16 hi/lo (swizzled), ssq partials
    {
        const float4* xg = (const float4*)eo;
        const int k4 = tid & 63;
        const int mb = tid >> 6;
#pragma unroll 4
        for (int it = 0; it < 32; it++) {
            int m = it * 4 + mb;
            float4 v = xg[(size_t)(r0 + m) * 64 + k4];
            uint32_t ph0 = packbf2f(v.x, v.y);
            uint32_t ph1 = packbf2f(v.z, v.w);
            uint32_t off = (uint32_t)(m * 512 + (((k4 >> 1) ^ (m & 7)) << 4) + ((k4 & 1) << 3));
            *(uint2*)(smem + OFF_AH + off) = make_uint2(ph0, ph1);
            float l0 = v.x - __uint_as_float(ph0 << 16);
            float l1 = v.y - __uint_as_float(ph0 & 0xffff0000u);
            float l2 = v.z - __uint_as_float(ph1 << 16);
            float l3 = v.w - __uint_as_float(ph1 & 0xffff0000u);
            *(uint2*)(smem + OFF_AL + off) = make_uint2(packbf2f(l0, l1), packbf2f(l2, l3));
            nsq_part[m * 65 + k4] = v.x * v.x + v.y * v.y + v.z * v.z + v.w * v.w;
        }
    }
    __syncthreads();

    // ---- norms: pull partials into registers before We prefetch clobbers them
    float nsum = 0.f;
    if (tid < 128) {
        const float* p = nsq_part + tid * 65;
#pragma unroll
        for (int i = 0; i < 64; i++) nsum += p[i];
    }
    __syncthreads();               // all nsq reads done; W buffer now free

    prefetch_w(sb, 0, tid);        // chunk 0 in flight

    if (tid < 128) {
        int r = r0 + tid;
        g_normT[(r & 31) * S_SZ + (r >> 5)] = sqrtf(nsum);
    }

    // ---- warp role: m32 group (4) x n32 half (2), full k256 per warp
    const int mg = w & 3;
    const int nh = w >> 2;
    const int t  = lane >> 3, rin = lane & 7;
    const int a_m0    = mg * 32 + ((t & 1) << 3) + rin;   // m-tile 0 row
    const int a_khalf = t >> 1;
    const uint32_t ab_h = sb + OFF_AH + (uint32_t)(a_m0 * 512);
    const uint32_t ab_l = sb + OFF_AL + (uint32_t)(a_m0 * 512);
    const int a_sw = a_m0 & 7;                            // (a_m0+16)&7 == a_m0&7
    const int b_n     = nh * 32 + ((t >> 1) << 3) + rin;  // n-group 0 row (0..63)
    const int b_khalf = t & 1;
    const uint32_t bb_h = sb + OFF_W + (uint32_t)(b_n * 512);
    const uint32_t bb_l = bb_h + 32768;
    const int b_sw = b_n & 7;                             // (b_n+16)&7 == b_n&7

    // output rows this thread touches
    const int rloc0 = mg * 32 + (lane >> 2);              // mt=0, rh=0
    const int qn    = (lane & 3) * 2;
    float ssum[2][2] = {{0.f, 0.f}, {0.f, 0.f}};          // [mt][rh]

    for (int c = 0; c < NCH; c++) {
        cp_wait0();
        __syncthreads();                  // We chunk c visible

        float acc[2][4][4];               // [mt][n8 0..3][frag]
#pragma unroll
        for (int mt = 0; mt < 2; mt++)
#pragma unroll
            for (int n8 = 0; n8 < 4; n8++)
#pragma unroll
                for (int q = 0; q < 4; q++) acc[mt][n8][q] = 0.f;

        uint32_t AH[2][2][4], AL[2][2][4], BH[2][2][4], BL[2][2][4];  // [buf][mt|g]
        {
            uint32_t ao = (uint32_t)((a_khalf ^ a_sw) << 4);
            uint32_t bo = (uint32_t)((b_khalf ^ b_sw) << 4);
            ldsm4(AH[0][0], ab_h + ao); ldsm4(AH[0][1], ab_h + 16 * 512 + ao);
            ldsm4(AL[0][0], ab_l + ao); ldsm4(AL[0][1], ab_l + 16 * 512 + ao);
            ldsm4(BH[0][0], bb_h + bo); ldsm4(BH[0][1], bb_h + 16 * 512 + bo);
            ldsm4(BL[0][0], bb_l + bo); ldsm4(BL[0][1], bb_l + 16 * 512 + bo);
        }
#pragma unroll
        for (int ks = 0; ks < 16; ks++) {
            const int cur = ks & 1, nxt = cur ^ 1;
            if (ks < 15) {
                int ck = (ks + 1) * 2;
                uint32_t ao = (uint32_t)(((ck + a_khalf) ^ a_sw) << 4);
                uint32_t bo = (uint32_t)(((ck + b_khalf) ^ b_sw) << 4);
                ldsm4(AH[nxt][0], ab_h + ao); ldsm4(AH[nxt][1], ab_h + 16 * 512 + ao);
                ldsm4(AL[nxt][0], ab_l + ao); ldsm4(AL[nxt][1], ab_l + 16 * 512 + ao);
                ldsm4(BH[nxt][0], bb_h + bo); ldsm4(BH[nxt][1], bb_h + 16 * 512 + bo);
                ldsm4(BL[nxt][0], bb_l + bo); ldsm4(BL[nxt][1], bb_l + 16 * 512 + bo);
            }
#pragma unroll
            for (int mt = 0; mt < 2; mt++)
#pragma unroll
                for (int g = 0; g < 2; g++) {
                    // hi*hi
                    mma16816(acc[mt][g * 2 + 0], AH[cur][mt], BH[cur][g][0], BH[cur][g][1]);
                    mma16816(acc[mt][g * 2 + 1], AH[cur][mt], BH[cur][g][2], BH[cur][g][3]);
                    // hi*lo
                    mma16816(acc[mt][g * 2 + 0], AH[cur][mt], BL[cur][g][0], BL[cur][g][1]);
                    mma16816(acc[mt][g * 2 + 1], AH[cur][mt], BL[cur][g][2], BL[cur][g][3]);
                    // lo*hi
                    mma16816(acc[mt][g * 2 + 0], AL[cur][mt], BH[cur][g][0], BH[cur][g][1]);
                    mma16816(acc[mt][g * 2 + 1], AL[cur][mt], BH[cur][g][2], BH[cur][g][3]);
                }
        }
        __syncthreads();                  // all warps done reading We chunk c

        // prefetch next chunk; latency overlaps the tanh epilogue below
        if (c + 1 < NCH) prefetch_w(sb, c + 1, tid);

        // ---- tanh epilogue: this warp's m32 x n32 fragment of chunk c
#pragma unroll
        for (int mt = 0; mt < 2; mt++) {
            const float* prow_lo = g_proj + ((rloc0 + mt * 16) & 31) * 256;
            const float* prow_hi = g_proj + ((rloc0 + mt * 16 + 8) & 31) * 256;
#pragma unroll
            for (int n8 = 0; n8 < 4; n8++) {
                int col = c * NCHUNK + nh * 32 + n8 * 8 + qn;
                float2 pl = __ldg((const float2*)(prow_lo + col));
                float2 ph = __ldg((const float2*)(prow_hi + col));
                ssum[mt][0] += tanh_fast(acc[mt][n8][0] + pl.x) + tanh_fast(acc[mt][n8][1] + pl.y);
                ssum[mt][1] += tanh_fast(acc[mt][n8][2] + ph.x) + tanh_fast(acc[mt][n8][3] + ph.y);
            }
        }
    }

    // ---- reduce 4 lanes per row, combine the two n-half warps via smem
#pragma unroll
    for (int mt = 0; mt < 2; mt++)
#pragma unroll
        for (int rh = 0; rh < 2; rh++) {
            float v = ssum[mt][rh];
            v += __shfl_xor_sync(0xffffffffu, v, 1);
            v += __shfl_xor_sync(0xffffffffu, v, 2);
            if ((lane & 3) == 0)
                sc_part[nh * 128 + rloc0 + mt * 16 + rh * 8] = v;
        }
    __syncthreads();
    if (tid < 128) {
        int r = r0 + tid;
        g_scoresT[(r & 31) * S_SZ + (r >> 5)] = sc_part[tid] + sc_part[128 + tid];
    }
}

// ============================ kernel 4: softmax stats ======================
__global__ void stats_kernel() {
    int b = blockIdx.x, t = threadIdx.x;
    __shared__ float red[256];
    const float* sc = g_scoresT + b * S_SZ;
    float m = -1e30f;
#pragma unroll 4
    for (int s = t; s < S_SZ; s += 256) m = fmaxf(m, sc[s]);
    red[t] = m; __syncthreads();
    for (int o = 128; o; o >>= 1) { if (t < o) red[t] = fmaxf(red[t], red[t + o]); __syncthreads(); }
    float smax = red[0]; __syncthreads();
    float sum = 0.f;
#pragma unroll 4
    for (int s = t; s < S_SZ; s += 256) sum += __expf(sc[s] - smax);
    red[t] = sum; __syncthreads();
    for (int o = 128; o; o >>= 1) { if (t < o) red[t] += red[t + o]; __syncthreads(); }
    if (t == 0) { g_smax[b] = smax; g_sinv[b] = 1.f / red[0]; }
}

// ======= kernel 5: weights, attn_map, attended partial sums ================
__global__ void attn_kernel(const float* __restrict__ eo, float* __restrict__ out) {
    int sc = blockIdx.x, b = blockIdx.y, t = threadIdx.x;
    __shared__ float wsm[256];
    float smax = g_smax[b], sinv = g_sinv[b];
    int s0 = sc * 256;
    int s = s0 + t;
    float wgt = __expf(g_scoresT[b * S_SZ + s] - smax) * sinv;
    wsm[t] = wgt;
    out[8192 + b * S_SZ + s] = wgt * g_normT[b * S_SZ + s];   // attn_map[b][s]
    __syncthreads();
    const float* base = eo + (size_t)s0 * (B_SZ * E_SZ) + b * E_SZ + t;
    float acc = 0.f;
#pragma unroll 16
    for (int s2 = 0; s2 < 256; s2++)
        acc = fmaf(wsm[s2], base[(size_t)s2 * (B_SZ * E_SZ)], acc);
    g_attpart[(b * NSC + sc) * E_SZ + t] = acc;
}

// ============================ kernel 6: final reduce =======================
__global__ void reduce_kernel(float* __restrict__ out) {
    int b = blockIdx.x, t = threadIdx.x;
    float a = 0.f;
#pragma unroll
    for (int sc = 0; sc < NSC; sc++) a += g_attpart[(b * NSC + sc) * E_SZ + t];
    out[b * E_SZ + t] = a;   // attended[b][e]
}

// ============================ launcher =====================================
extern "C" void kernel_launch(void* const* d_in, const int* in_sizes, int n_in,
                              void* d_out, int out_size) {
    const float* dh   = (const float*)d_in[0];  // (1,B,D)
    const float* eo   = (const float*)d_in[1];  // (S,B,E)
    const float* W    = (const float*)d_in[2];  // (A, D+E)
    const float* bias = (const float*)d_in[3];  // (A,)
    float* out = (float*)d_out;                 // [attended(32x256) | attn_map(32x4096)]

    cudaFuncSetAttribute(phase1_kernel, cudaFuncAttributeMaxDynamicSharedMemorySize, SMEM_P1);

    splitw_kernel<<<256, 256>>>(W);
    proj_kernel<<<32, 256>>>(dh, W, bias);
    dummy_kernel<<<1, 32>>>();                  // shifts phase1 into ncu's profiled slot
    phase1_kernel<<<NTILES, 256, SMEM_P1>>>(eo);
    stats_kernel<<<32, 256>>>();
    attn_kernel<<<dim3(NSC, 32), 256>>>(eo, out);
    reduce_kernel<<<32, 256>>>(out);
}